// round 14
// baseline (speedup 1.0000x reference)
#include <cuda_runtime.h>
#include <cstdint>

#define BATCH 32768

// ---------------- scratch (static device globals; no allocs allowed) ----------------
__device__ __align__(16) float g_buf0[BATCH * 1024];
__device__ __align__(16) float g_buf1[BATCH * 1024];
__device__ __align__(16) float g_x4n [BATCH * 512];
__device__ __align__(16) float g_xn  [BATCH * 256];   // tf32-rounded node_x
__device__ __align__(16) float g_xl  [BATCH * 16];    // tf32-rounded layer_x
__device__ __align__(16) float g_wt  [2428928];       // tf32-rounded weights (8 mats)
__device__ __align__(16) float g_wn[512];
__device__ __align__(16) float g_wl[512];
__device__ float g_sc[2];   // [0]=bn (mean of nb5), [1]=bl (wreg . lb5)

// weight offsets inside g_wt
#define OFF_NW1 0
#define OFF_NW2 65536
#define OFF_NW3 196608
#define OFF_NW4 720896
#define OFF_LW1 1245184
#define OFF_LW2 1249280
#define OFF_LW3 1380352
#define OFF_LW4 1904640

// cvt.rna.tf32.f32: destination is a .b32 register -> "=r".
__device__ __forceinline__ uint32_t f32_to_tf32_rna(float x) {
    uint32_t r;
    asm("cvt.rna.tf32.f32 %0, %1;" : "=r"(r) : "f"(x));
    return r;
}
__device__ __forceinline__ float tf32r(float x) {
    return __uint_as_float(f32_to_tf32_rna(x));
}

__device__ __forceinline__ uint32_t smem_u32(const void* p) {
    uint32_t a;
    asm("{ .reg .u64 t; cvta.to.shared.u64 t, %1; cvt.u32.u64 %0, t; }" : "=r"(a) : "l"(p));
    return a;
}

// cp.async 16B with register src-size (0 => zero-fill 16B)
__device__ __forceinline__ void cp16(uint32_t dst, const void* src, int src_size) {
    asm volatile("cp.async.cg.shared.global [%0], [%1], 16, %2;"
                 :: "r"(dst), "l"(src), "r"(src_size));
}
#define CP_COMMIT() asm volatile("cp.async.commit_group;" ::: "memory")
#define CP_WAIT0()  asm volatile("cp.async.wait_group 0;" ::: "memory")
#define CP_WAIT1()  asm volatile("cp.async.wait_group 1;" ::: "memory")

// ldmatrix: 8x8 b16 tiles == 8x4 b32 tiles; lane l of consumer gets word (row l/4, col l%4).
__device__ __forceinline__ void ldsm_x4(uint32_t& r0, uint32_t& r1, uint32_t& r2, uint32_t& r3,
                                        uint32_t addr) {
    asm volatile("ldmatrix.sync.aligned.m8n8.x4.shared.b16 {%0,%1,%2,%3}, [%4];"
                 : "=r"(r0), "=r"(r1), "=r"(r2), "=r"(r3) : "r"(addr));
}

// ---------------- fused tf32-RNA rounding prepass (single launch) ----------------
struct CvtArgs {
    const float* src[10];
    float*       dst[10];
    int          n4[10];    // element count / 4
};

__global__ __launch_bounds__(256)
void cvt_all_kernel(CvtArgs a)
{
    const int tid    = blockIdx.x * 256 + threadIdx.x;
    const int stride = gridDim.x * 256;
    #pragma unroll
    for (int s = 0; s < 10; ++s) {
        const float4* sp = (const float4*)a.src[s];
        float4*       dp = (float4*)a.dst[s];
        const int n4 = a.n4[s];
        for (int i = tid; i < n4; i += stride) {
            float4 v = sp[i];
            v.x = tf32r(v.x); v.y = tf32r(v.y); v.z = tf32r(v.z); v.w = tf32r(v.w);
            dp[i] = v;
        }
    }
}

// ---------------- head-collapse precompute ----------------
// w_n[k] = mean_o nW5[o,k]; w_l[k] = sum_o wreg[o]*lW5[o,k]
__global__ void precompute_head(const float* __restrict__ nW5, const float* __restrict__ nb5,
                                const float* __restrict__ lW5, const float* __restrict__ lb5,
                                const float* __restrict__ wreg)
{
    int k = threadIdx.x;                // 512 threads
    float s1 = 0.f, s2 = 0.f;
    #pragma unroll 4
    for (int o = 0; o < 256; ++o) {
        s1 += nW5[o * 512 + k];
        s2 += wreg[o] * lW5[o * 512 + k];
    }
    g_wn[k] = s1 * (1.f / 256.f);
    g_wl[k] = s2;
    if (k == 0) {
        float b = 0.f;
        for (int o = 0; o < 256; ++o) b += nb5[o];
        g_sc[0] = b * (1.f / 256.f);
    }
    if (k == 1) {
        float b = 0.f;
        for (int o = 0; o < 256; ++o) b += wreg[o] * lb5[o];
        g_sc[1] = b;
    }
}

// ================= tf32 mma.sync GEMM v6 (4-warp CTA, 64x64 warp tile) ============
// C[M,N] = [tf32r](relu(A @ W^T + bias)); A, W pre-rounded tf32 bit patterns.
// CTA 128x128, BK=32, 128 threads (4 warps in 2x2, warp tile 64x64), 2 CTAs/SM.
// 32 independent MMAs per k8-step per warp; 8 LDSM (4 A.x4 + 4 B.x4) per k8-step.

#define PAD_STRIDE 36                    // words per 32-col row; 144B row stride, LDSM conflict-free
#define MAT_WORDS  (128 * PAD_STRIDE)    // 4608 words
#define MAT_BYTES  (MAT_WORDS * 4)       // 18432 B
#define BUF_BYTES  (2 * MAT_BYTES)       // A + B per buffer: 36864 B
#define NSTAGE     3
#define SMEM_BYTES (NSTAGE * BUF_BYTES)  // 110592 B

__device__ __forceinline__ void mma_tf32(float* c, const uint32_t* a, const uint32_t* b) {
    asm volatile(
        "mma.sync.aligned.m16n8k8.row.col.f32.tf32.tf32.f32 "
        "{%0,%1,%2,%3}, {%4,%5,%6,%7}, {%8,%9}, {%0,%1,%2,%3};"
        : "+f"(c[0]), "+f"(c[1]), "+f"(c[2]), "+f"(c[3])
        : "r"(a[0]), "r"(a[1]), "r"(a[2]), "r"(a[3]), "r"(b[0]), "r"(b[1]));
}

template <bool ROUND>
__global__ __launch_bounds__(128, 2)
void gemm_mma(const float* __restrict__ A, const float* __restrict__ W,
              const float* __restrict__ bias, float* __restrict__ C,
              int M, int N, int K)
{
    extern __shared__ float sm[];   // [stage][A|B][128][PAD_STRIDE]

    const int t    = threadIdx.x;
    const int lane = t & 31;
    const int wid  = t >> 5;            // 0..3
    const int bm   = blockIdx.y * 128;
    const int bn   = blockIdx.x * 128;
    const int wm   = (wid >> 1) * 64;   // warp M offset (0 or 64)
    const int wn   = (wid & 1) * 64;    // warp N offset (0 or 64)
    const int gid  = lane >> 2;         // 0..7
    const int tg   = lane & 3;          // 0..3

    // async-copy geometry: 1024 x 16B per matrix tile; 8 per thread per matrix
    const int g_row = t >> 3;           // base row 0..15 (+16*j)
    const int g_c4  = (t & 7) << 2;     // k word offset 0,4,...,28

    const uint32_t sbase = smem_u32(sm);
    const uint32_t d_off = (uint32_t)(g_row * PAD_STRIDE + g_c4) * 4;

    // ldmatrix per-lane byte offsets (relative to matrix base)
    // A (.x4) tile mi: row = wm+16*mi+(lane&15), col-half = (lane>>4)*4 words
    //   -> regs: a0=(g,tg) a1=(g+8,tg) a2=(g,tg+4) a3=(g+8,tg+4)
    // B (.x4) pair nj (n-tiles 2nj, 2nj+1): row = wn+16*nj+(lane&7)+((lane>>4)<<3),
    //   col-half = ((lane>>3)&1)*4 words
    //   -> regs: r0,r1 = b0,b1 of tile 2nj ; r2,r3 = b0,b1 of tile 2nj+1
    uint32_t a_off[4], b_off[4];
    {
        const int ar = lane & 15;
        const int ac = (lane >> 4) << 2;
        const int br = (lane & 7) + ((lane >> 4) << 3);
        const int bc = ((lane >> 3) & 1) << 2;
        #pragma unroll
        for (int mi = 0; mi < 4; ++mi)
            a_off[mi] = (uint32_t)(((wm + (mi << 4) + ar) * PAD_STRIDE + ac) * 4);
        #pragma unroll
        for (int nj = 0; nj < 4; ++nj)
            b_off[nj] = (uint32_t)(((wn + (nj << 4) + br) * PAD_STRIDE + bc) * 4);
    }

    float acc[4][8][4] = {};            // [mi][ni][c0..c3]
    const int nkt = (K + 31) >> 5;

    auto cp_tile = [&](int kt, int buf) {
        const int k0 = kt << 5;
        const bool ok = (k0 + g_c4 + 3) < K;
        const int sz = ok ? 16 : 0;
        const int koff = ok ? (k0 + g_c4) : 0;       // safe base when zero-filling
        const uint32_t dA = sbase + buf * BUF_BYTES + d_off;
        const uint32_t dB = dA + MAT_BYTES;
        const float* Ap = A + (long)(bm + g_row) * K + koff;
        const float* Wp = W + (long)(bn + g_row) * K + koff;
        #pragma unroll
        for (int j = 0; j < 8; ++j) {
            cp16(dA + j * 16 * (PAD_STRIDE * 4), Ap + (long)j * 16 * K, sz);
            cp16(dB + j * 16 * (PAD_STRIDE * 4), Wp + (long)j * 16 * K, sz);
        }
    };

    // ---- prologue: stage tiles 0 and 1 ----
    cp_tile(0, 0);
    CP_COMMIT();
    if (1 < nkt) { cp_tile(1, 1); CP_COMMIT(); }

    int buf = 0;
    for (int kt = 0; kt < nkt; ++kt) {
        // tile kt complete when <=1 newer group pending (kt+1); at tail, 0.
        if (kt + 1 < nkt) CP_WAIT1(); else CP_WAIT0();
        __syncthreads();                 // data visible + tile kt-1 readers retired

        if (kt + 2 < nkt) {              // prefetch into buffer of retired tile kt-1
            cp_tile(kt + 2, (buf + 2 >= NSTAGE) ? (buf + 2 - NSTAGE) : (buf + 2));
            CP_COMMIT();
        }

        const uint32_t as_u = sbase + buf * BUF_BYTES;
        const uint32_t bs_u = as_u + MAT_BYTES;

        #pragma unroll
        for (int ks = 0; ks < 4; ++ks) {
            const uint32_t kb = (uint32_t)(ks << 5);   // kc*4 bytes, kc = 8*ks
            uint32_t af[4][4], bf[8][2];
            #pragma unroll
            for (int mi = 0; mi < 4; ++mi)
                ldsm_x4(af[mi][0], af[mi][1], af[mi][2], af[mi][3], as_u + a_off[mi] + kb);
            #pragma unroll
            for (int nj = 0; nj < 4; ++nj)
                ldsm_x4(bf[2*nj][0], bf[2*nj][1], bf[2*nj+1][0], bf[2*nj+1][1],
                        bs_u + b_off[nj] + kb);
            #pragma unroll
            for (int mi = 0; mi < 4; ++mi)
                #pragma unroll
                for (int ni = 0; ni < 8; ++ni)
                    mma_tf32(acc[mi][ni], af[mi], bf[ni]);
        }

        buf = (buf + 1 == NSTAGE) ? 0 : (buf + 1);
    }

    // ---- epilogue: bias + relu (+ tf32 round), float2 stores ----
    #pragma unroll
    for (int mi = 0; mi < 4; ++mi) {
        const long row0 = bm + wm + (mi << 4) + gid;
        const long row1 = row0 + 8;
        #pragma unroll
        for (int ni = 0; ni < 8; ++ni) {
            const int col = bn + wn + (ni << 3) + (tg << 1);
            const float b0 = __ldg(bias + col);
            const float b1 = __ldg(bias + col + 1);
            float2 lo, hi;
            lo.x = fmaxf(acc[mi][ni][0] + b0, 0.f);
            lo.y = fmaxf(acc[mi][ni][1] + b1, 0.f);
            hi.x = fmaxf(acc[mi][ni][2] + b0, 0.f);
            hi.y = fmaxf(acc[mi][ni][3] + b1, 0.f);
            if (ROUND) {
                lo.x = tf32r(lo.x); lo.y = tf32r(lo.y);
                hi.x = tf32r(hi.x); hi.y = tf32r(hi.y);
            }
            *(float2*)(C + row0 * N + col) = lo;
            *(float2*)(C + row1 * N + col) = hi;
        }
    }
}

// ---------------- fused head: out[b] = (x4n[b].wn + bn) * (x4l[b].wl + bl) ----------------
__global__ __launch_bounds__(256)
void head_kernel(const float* __restrict__ xn, const float* __restrict__ xl,
                 float* __restrict__ out)
{
    int warp = (blockIdx.x * 256 + threadIdx.x) >> 5;
    int lane = threadIdx.x & 31;
    if (warp >= BATCH) return;

    const float4* pn = (const float4*)(xn + (long)warp * 512);
    const float4* pl = (const float4*)(xl + (long)warp * 512);
    const float4* wn = (const float4*)g_wn;
    const float4* wl = (const float4*)g_wl;

    float sn = 0.f, sl = 0.f;
    #pragma unroll
    for (int i = lane; i < 128; i += 32) {
        float4 a = pn[i], w = wn[i];
        sn += a.x * w.x + a.y * w.y + a.z * w.z + a.w * w.w;
        float4 b = pl[i], v = wl[i];
        sl += b.x * v.x + b.y * v.y + b.z * v.z + b.w * v.w;
    }
    #pragma unroll
    for (int off = 16; off > 0; off >>= 1) {
        sn += __shfl_xor_sync(0xffffffffu, sn, off);
        sl += __shfl_xor_sync(0xffffffffu, sl, off);
    }
    if (lane == 0)
        out[warp] = (sn + g_sc[0]) * (sl + g_sc[1]);
}

// ---------------- launch ----------------
extern "C" void kernel_launch(void* const* d_in, const int* in_sizes, int n_in,
                              void* d_out, int out_size)
{
    const float* node_x = (const float*)d_in[0];   // [B,256]
    const float* layer_x= (const float*)d_in[1];   // [B,16]
    const float* nW1 = (const float*)d_in[2];  const float* nb1 = (const float*)d_in[3];
    const float* nW2 = (const float*)d_in[4];  const float* nb2 = (const float*)d_in[5];
    const float* nW3 = (const float*)d_in[6];  const float* nb3 = (const float*)d_in[7];
    const float* nW4 = (const float*)d_in[8];  const float* nb4 = (const float*)d_in[9];
    const float* nW5 = (const float*)d_in[10]; const float* nb5 = (const float*)d_in[11];
    const float* lW1 = (const float*)d_in[12]; const float* lb1 = (const float*)d_in[13];
    const float* lW2 = (const float*)d_in[14]; const float* lb2 = (const float*)d_in[15];
    const float* lW3 = (const float*)d_in[16]; const float* lb3 = (const float*)d_in[17];
    const float* lW4 = (const float*)d_in[18]; const float* lb4 = (const float*)d_in[19];
    const float* lW5 = (const float*)d_in[20]; const float* lb5 = (const float*)d_in[21];
    const float* wreg= (const float*)d_in[22]; // [256]
    float* out = (float*)d_out;

    float *buf0, *buf1, *x4n, *xn, *xl, *wt;
    cudaGetSymbolAddress((void**)&buf0, g_buf0);
    cudaGetSymbolAddress((void**)&buf1, g_buf1);
    cudaGetSymbolAddress((void**)&x4n,  g_x4n);
    cudaGetSymbolAddress((void**)&xn,   g_xn);
    cudaGetSymbolAddress((void**)&xl,   g_xl);
    cudaGetSymbolAddress((void**)&wt,   g_wt);

    const int M = BATCH;
    cudaFuncSetAttribute(gemm_mma<true>,  cudaFuncAttributeMaxDynamicSharedMemorySize, SMEM_BYTES);
    cudaFuncSetAttribute(gemm_mma<false>, cudaFuncAttributeMaxDynamicSharedMemorySize, SMEM_BYTES);

    const dim3 gemm_blk(128);   // gemm_mma CTA size
    const dim3 head_blk(256);   // head_kernel CTA size (grid math below assumes 256!)

    // launch 1: head precompute
    precompute_head<<<1, 512>>>(nW5, nb5, lW5, lb5, wreg);

    // launch 2: fused tf32-RNA prepass (inputs + weights)
    CvtArgs ca;
    ca.src[0] = node_x;  ca.dst[0] = xn;            ca.n4[0] = BATCH * 256 / 4;
    ca.src[1] = layer_x; ca.dst[1] = xl;            ca.n4[1] = BATCH * 16 / 4;
    ca.src[2] = nW1;     ca.dst[2] = wt + OFF_NW1;  ca.n4[2] = 256 * 256 / 4;
    ca.src[3] = nW2;     ca.dst[3] = wt + OFF_NW2;  ca.n4[3] = 512 * 256 / 4;
    ca.src[4] = nW3;     ca.dst[4] = wt + OFF_NW3;  ca.n4[4] = 1024 * 512 / 4;
    ca.src[5] = nW4;     ca.dst[5] = wt + OFF_NW4;  ca.n4[5] = 512 * 1024 / 4;
    ca.src[6] = lW1;     ca.dst[6] = wt + OFF_LW1;  ca.n4[6] = 256 * 16 / 4;
    ca.src[7] = lW2;     ca.dst[7] = wt + OFF_LW2;  ca.n4[7] = 512 * 256 / 4;
    ca.src[8] = lW3;     ca.dst[8] = wt + OFF_LW3;  ca.n4[8] = 1024 * 512 / 4;
    ca.src[9] = lW4;     ca.dst[9] = wt + OFF_LW4;  ca.n4[9] = 512 * 1024 / 4;
    cvt_all_kernel<<<2048, 256>>>(ca);

    // launches 3-6: node tower (relu layers 1-4; layer 5 collapsed into head)
    gemm_mma<true ><<<dim3(256/128,  M/128), gemm_blk, SMEM_BYTES>>>(xn,   wt + OFF_NW1, nb1, buf0, M, 256, 256);
    gemm_mma<true ><<<dim3(512/128,  M/128), gemm_blk, SMEM_BYTES>>>(buf0, wt + OFF_NW2, nb2, buf1, M, 512, 256);
    gemm_mma<true ><<<dim3(1024/128, M/128), gemm_blk, SMEM_BYTES>>>(buf1, wt + OFF_NW3, nb3, buf0, M, 1024, 512);
    gemm_mma<false><<<dim3(512/128,  M/128), gemm_blk, SMEM_BYTES>>>(buf0, wt + OFF_NW4, nb4, x4n,  M, 512, 1024);

    // launches 7-10: layer tower
    gemm_mma<true ><<<dim3(256/128,  M/128), gemm_blk, SMEM_BYTES>>>(xl,   wt + OFF_LW1, lb1, buf0, M, 256, 16);
    gemm_mma<true ><<<dim3(512/128,  M/128), gemm_blk, SMEM_BYTES>>>(buf0, wt + OFF_LW2, lb2, buf1, M, 512, 256);
    gemm_mma<true ><<<dim3(1024/128, M/128), gemm_blk, SMEM_BYTES>>>(buf1, wt + OFF_LW3, lb3, buf0, M, 1024, 512);
    gemm_mma<false><<<dim3(512/128,  M/128), gemm_blk, SMEM_BYTES>>>(buf0, wt + OFF_LW4, lb4, buf1, M, 512, 1024);

    // launch 11: fused collapsed head — grid sized for 256-thread blocks (8 warps/block)
    head_kernel<<<(BATCH * 32) / 256, head_blk>>>(x4n, buf1, out);
}

// round 16
// speedup vs baseline: 1.7900x; 1.7900x over previous
#include <cuda_runtime.h>
#include <cuda_fp16.h>
#include <cstdint>

#define BATCH 32768

// ---------------- scratch (static device globals; no allocs allowed) ----------------
__device__ __align__(16) __half h_buf0[BATCH * 1024];   // fp16 intermediates
__device__ __align__(16) __half h_buf1[BATCH * 1024];
__device__ __align__(16) float  g_x4n [BATCH * 512];    // node tower final (f32, head input)
__device__ __align__(16) float  g_x4l [BATCH * 512];    // layer tower final (f32, head input)
__device__ __align__(16) __half h_xn  [BATCH * 256];    // fp16 node_x
__device__ __align__(16) __half h_xl  [BATCH * 16];     // fp16 layer_x
__device__ __align__(16) __half h_wt  [2428928];        // fp16 weights (8 mats)
__device__ __align__(16) float  g_wn[512];
__device__ __align__(16) float  g_wl[512];
__device__ float g_sc[2];   // [0]=bn (mean of nb5), [1]=bl (wreg . lb5)

// weight offsets inside h_wt
#define OFF_NW1 0
#define OFF_NW2 65536
#define OFF_NW3 196608
#define OFF_NW4 720896
#define OFF_LW1 1245184
#define OFF_LW2 1249280
#define OFF_LW3 1380352
#define OFF_LW4 1904640

__device__ __forceinline__ uint32_t smem_u32(const void* p) {
    uint32_t a;
    asm("{ .reg .u64 t; cvta.to.shared.u64 t, %1; cvt.u32.u64 %0, t; }" : "=r"(a) : "l"(p));
    return a;
}

// cp.async 16B with register src-size (0 => zero-fill 16B)
__device__ __forceinline__ void cp16(uint32_t dst, const void* src, int src_size) {
    asm volatile("cp.async.cg.shared.global [%0], [%1], 16, %2;"
                 :: "r"(dst), "l"(src), "r"(src_size));
}
#define CP_COMMIT() asm volatile("cp.async.commit_group;" ::: "memory")
#define CP_WAIT0()  asm volatile("cp.async.wait_group 0;" ::: "memory")
#define CP_WAIT1()  asm volatile("cp.async.wait_group 1;" ::: "memory")

// ldmatrix m8n8.b16: lane l gets 2 halves at (row l/4, cols 2(l%4)..+1) of each 8x8 tile.
__device__ __forceinline__ void ldsm_x4(uint32_t& r0, uint32_t& r1, uint32_t& r2, uint32_t& r3,
                                        uint32_t addr) {
    asm volatile("ldmatrix.sync.aligned.m8n8.x4.shared.b16 {%0,%1,%2,%3}, [%4];"
                 : "=r"(r0), "=r"(r1), "=r"(r2), "=r"(r3) : "r"(addr));
}

// ---------------- fused f32->fp16 rounding prepass (single launch) ----------------
struct CvtArgs {
    const float* src[10];
    __half*      dst[10];
    int          n4[10];    // element count / 4
};

__global__ __launch_bounds__(256)
void cvt_all_kernel(CvtArgs a)
{
    const int tid    = blockIdx.x * 256 + threadIdx.x;
    const int stride = gridDim.x * 256;
    #pragma unroll
    for (int s = 0; s < 10; ++s) {
        const float4* sp = (const float4*)a.src[s];
        __half2*      dp = (__half2*)a.dst[s];
        const int n4 = a.n4[s];
        for (int i = tid; i < n4; i += stride) {
            float4 v = sp[i];
            dp[2*i]   = __floats2half2_rn(v.x, v.y);
            dp[2*i+1] = __floats2half2_rn(v.z, v.w);
        }
    }
}

// ---------------- head-collapse precompute ----------------
// w_n[k] = mean_o nW5[o,k]; w_l[k] = sum_o wreg[o]*lW5[o,k]
__global__ void precompute_head(const float* __restrict__ nW5, const float* __restrict__ nb5,
                                const float* __restrict__ lW5, const float* __restrict__ lb5,
                                const float* __restrict__ wreg)
{
    int k = threadIdx.x;                // 512 threads
    float s1 = 0.f, s2 = 0.f;
    #pragma unroll 4
    for (int o = 0; o < 256; ++o) {
        s1 += nW5[o * 512 + k];
        s2 += wreg[o] * lW5[o * 512 + k];
    }
    g_wn[k] = s1 * (1.f / 256.f);
    g_wl[k] = s2;
    if (k == 0) {
        float b = 0.f;
        for (int o = 0; o < 256; ++o) b += nb5[o];
        g_sc[0] = b * (1.f / 256.f);
    }
    if (k == 1) {
        float b = 0.f;
        for (int o = 0; o < 256; ++o) b += wreg[o] * lb5[o];
        g_sc[1] = b;
    }
}

// ================= fp16 mma.sync GEMM v7 (m16n8k16, BK=64) ============
// C[M,N] = relu(A @ W^T + bias); A, W fp16 (rn-rounded), f32 accumulate.
// F32OUT: C is float (head inputs); else C is __half (next layer's A).
// CTA 128x128, BK=64, 128 threads (4 warps 2x2, warp tile 64x64), 2 CTAs/SM.
// 3-stage cp.async, 1 sync/tile; per k16-step: 8 ldsm.x4 + 32 MMA per warp.

#define ROW_H      72                       // halves per row (64 + 8 pad); 144B stride
#define MAT_BYTES  (128 * ROW_H * 2)        // 18432 B
#define BUF_BYTES  (2 * MAT_BYTES)          // A + B per buffer: 36864 B
#define NSTAGE     3
#define SMEM_BYTES (NSTAGE * BUF_BYTES)     // 110592 B

__device__ __forceinline__ void mma_f16(float* c, const uint32_t* a, const uint32_t* b) {
    asm volatile(
        "mma.sync.aligned.m16n8k16.row.col.f32.f16.f16.f32 "
        "{%0,%1,%2,%3}, {%4,%5,%6,%7}, {%8,%9}, {%0,%1,%2,%3};"
        : "+f"(c[0]), "+f"(c[1]), "+f"(c[2]), "+f"(c[3])
        : "r"(a[0]), "r"(a[1]), "r"(a[2]), "r"(a[3]), "r"(b[0]), "r"(b[1]));
}

template <bool F32OUT>
__global__ __launch_bounds__(128, 2)
void gemm_mma(const __half* __restrict__ A, const __half* __restrict__ W,
              const float* __restrict__ bias, void* __restrict__ Cv,
              int M, int N, int K)
{
    extern __shared__ __half sm[];   // [stage][A|B][128][ROW_H]

    const int t    = threadIdx.x;
    const int lane = t & 31;
    const int wid  = t >> 5;            // 0..3
    const int bm   = blockIdx.y * 128;
    const int bn   = blockIdx.x * 128;
    const int wm   = (wid >> 1) * 64;   // warp M offset (0 or 64)
    const int wn   = (wid & 1) * 64;    // warp N offset (0 or 64)
    const int gid  = lane >> 2;         // 0..7
    const int tg   = lane & 3;          // 0..3

    // cp.async geometry: per matrix tile 128 rows x 64 halves = 1024 x 16B chunks;
    // 128 threads -> 8 chunks/thread/matrix.
    const int g_row = t >> 3;           // base row 0..15 (+16*j)
    const int g_c8  = (t & 7) << 3;     // k half-offset 0,8,...,56

    const uint32_t sbase = smem_u32(sm);
    const uint32_t d_off = (uint32_t)(g_row * ROW_H + g_c8) * 2;

    // ldmatrix per-lane byte offsets (relative to matrix base, 144B row stride)
    // A (.x4) tile mi (m16 x k16): row = wm+16mi+(lane&15), k-half = (lane>>4)*8 halves
    //   -> a0=(g,2tg) a1=(g+8,2tg) a2=(g,8+2tg) a3=(g+8,8+2tg)  [pairs of halves]
    // B (.x4) pair nj (n-tiles 2nj,2nj+1, each n8 x k16):
    //   row = wn+16nj+(lane&7)+((lane>>4)<<3), k-half = ((lane>>3)&1)*8
    //   -> r0,r1 = b0,b1 of n-tile 2nj ; r2,r3 = b0,b1 of n-tile 2nj+1
    uint32_t a_off[4], b_off[4];
    {
        const int ar = lane & 15;
        const int ac = (lane >> 4) << 3;                   // halves
        const int br = (lane & 7) + ((lane >> 4) << 3);
        const int bc = ((lane >> 3) & 1) << 3;             // halves
        #pragma unroll
        for (int mi = 0; mi < 4; ++mi)
            a_off[mi] = (uint32_t)(((wm + (mi << 4) + ar) * ROW_H + ac) * 2);
        #pragma unroll
        for (int nj = 0; nj < 4; ++nj)
            b_off[nj] = (uint32_t)(((wn + (nj << 4) + br) * ROW_H + bc) * 2);
    }

    float acc[4][8][4] = {};            // [mi][ni][c0..c3]
    const int nkt = (K + 63) >> 6;

    auto cp_tile = [&](int kt, int buf) {
        const int k0 = kt << 6;
        const bool ok = (k0 + g_c8 + 7) < K;
        const int sz = ok ? 16 : 0;
        const int koff = ok ? (k0 + g_c8) : 0;       // safe base when zero-filling
        const uint32_t dA = sbase + buf * BUF_BYTES + d_off;
        const uint32_t dB = dA + MAT_BYTES;
        const __half* Ap = A + (long)(bm + g_row) * K + koff;
        const __half* Wp = W + (long)(bn + g_row) * K + koff;
        #pragma unroll
        for (int j = 0; j < 8; ++j) {
            cp16(dA + j * 16 * (ROW_H * 2), Ap + (long)j * 16 * K, sz);
            cp16(dB + j * 16 * (ROW_H * 2), Wp + (long)j * 16 * K, sz);
        }
    };

    // ---- prologue: stage tiles 0 and 1 ----
    cp_tile(0, 0);
    CP_COMMIT();
    if (1 < nkt) { cp_tile(1, 1); CP_COMMIT(); }

    int buf = 0;
    for (int kt = 0; kt < nkt; ++kt) {
        if (kt + 1 < nkt) CP_WAIT1(); else CP_WAIT0();
        __syncthreads();                 // data visible + tile kt-1 readers retired

        if (kt + 2 < nkt) {              // prefetch into buffer of retired tile kt-1
            cp_tile(kt + 2, (buf + 2 >= NSTAGE) ? (buf + 2 - NSTAGE) : (buf + 2));
            CP_COMMIT();
        }

        const uint32_t as_u = sbase + buf * BUF_BYTES;
        const uint32_t bs_u = as_u + MAT_BYTES;

        #pragma unroll
        for (int ks = 0; ks < 4; ++ks) {
            const uint32_t kb = (uint32_t)(ks << 5);   // 16 halves * 2B per k16-step
            uint32_t af[4][4], bf[8][2];
            #pragma unroll
            for (int mi = 0; mi < 4; ++mi)
                ldsm_x4(af[mi][0], af[mi][1], af[mi][2], af[mi][3], as_u + a_off[mi] + kb);
            #pragma unroll
            for (int nj = 0; nj < 4; ++nj)
                ldsm_x4(bf[2*nj][0], bf[2*nj][1], bf[2*nj+1][0], bf[2*nj+1][1],
                        bs_u + b_off[nj] + kb);
            #pragma unroll
            for (int mi = 0; mi < 4; ++mi)
                #pragma unroll
                for (int ni = 0; ni < 8; ++ni)
                    mma_f16(acc[mi][ni], af[mi], bf[ni]);
        }

        buf = (buf + 1 == NSTAGE) ? 0 : (buf + 1);
    }

    // ---- epilogue: bias + relu; store f32 (head input) or fp16 (next layer) ----
    #pragma unroll
    for (int mi = 0; mi < 4; ++mi) {
        const long row0 = bm + wm + (mi << 4) + gid;
        const long row1 = row0 + 8;
        #pragma unroll
        for (int ni = 0; ni < 8; ++ni) {
            const int col = bn + wn + (ni << 3) + (tg << 1);
            const float b0 = __ldg(bias + col);
            const float b1 = __ldg(bias + col + 1);
            float v0 = fmaxf(acc[mi][ni][0] + b0, 0.f);
            float v1 = fmaxf(acc[mi][ni][1] + b1, 0.f);
            float v2 = fmaxf(acc[mi][ni][2] + b0, 0.f);
            float v3 = fmaxf(acc[mi][ni][3] + b1, 0.f);
            if (F32OUT) {
                float* C = (float*)Cv;
                *(float2*)(C + row0 * N + col) = make_float2(v0, v1);
                *(float2*)(C + row1 * N + col) = make_float2(v2, v3);
            } else {
                __half* C = (__half*)Cv;
                *(__half2*)(C + row0 * N + col) = __floats2half2_rn(v0, v1);
                *(__half2*)(C + row1 * N + col) = __floats2half2_rn(v2, v3);
            }
        }
    }
}

// ---------------- fused head: out[b] = (x4n[b].wn + bn) * (x4l[b].wl + bl) ----------------
__global__ __launch_bounds__(256)
void head_kernel(const float* __restrict__ xn, const float* __restrict__ xl,
                 float* __restrict__ out)
{
    int warp = (blockIdx.x * 256 + threadIdx.x) >> 5;
    int lane = threadIdx.x & 31;
    if (warp >= BATCH) return;

    const float4* pn = (const float4*)(xn + (long)warp * 512);
    const float4* pl = (const float4*)(xl + (long)warp * 512);
    const float4* wn = (const float4*)g_wn;
    const float4* wl = (const float4*)g_wl;

    float sn = 0.f, sl = 0.f;
    #pragma unroll
    for (int i = lane; i < 128; i += 32) {
        float4 a = pn[i], w = wn[i];
        sn += a.x * w.x + a.y * w.y + a.z * w.z + a.w * w.w;
        float4 b = pl[i], v = wl[i];
        sl += b.x * v.x + b.y * v.y + b.z * v.z + b.w * v.w;
    }
    #pragma unroll
    for (int off = 16; off > 0; off >>= 1) {
        sn += __shfl_xor_sync(0xffffffffu, sn, off);
        sl += __shfl_xor_sync(0xffffffffu, sl, off);
    }
    if (lane == 0)
        out[warp] = (sn + g_sc[0]) * (sl + g_sc[1]);
}

// ---------------- launch ----------------
extern "C" void kernel_launch(void* const* d_in, const int* in_sizes, int n_in,
                              void* d_out, int out_size)
{
    const float* node_x = (const float*)d_in[0];   // [B,256]
    const float* layer_x= (const float*)d_in[1];   // [B,16]
    const float* nW1 = (const float*)d_in[2];  const float* nb1 = (const float*)d_in[3];
    const float* nW2 = (const float*)d_in[4];  const float* nb2 = (const float*)d_in[5];
    const float* nW3 = (const float*)d_in[6];  const float* nb3 = (const float*)d_in[7];
    const float* nW4 = (const float*)d_in[8];  const float* nb4 = (const float*)d_in[9];
    const float* nW5 = (const float*)d_in[10]; const float* nb5 = (const float*)d_in[11];
    const float* lW1 = (const float*)d_in[12]; const float* lb1 = (const float*)d_in[13];
    const float* lW2 = (const float*)d_in[14]; const float* lb2 = (const float*)d_in[15];
    const float* lW3 = (const float*)d_in[16]; const float* lb3 = (const float*)d_in[17];
    const float* lW4 = (const float*)d_in[18]; const float* lb4 = (const float*)d_in[19];
    const float* lW5 = (const float*)d_in[20]; const float* lb5 = (const float*)d_in[21];
    const float* wreg= (const float*)d_in[22]; // [256]
    float* out = (float*)d_out;

    __half *b0h, *b1h, *xn, *xl, *wt;
    float *x4n, *x4l;
    cudaGetSymbolAddress((void**)&b0h, h_buf0);
    cudaGetSymbolAddress((void**)&b1h, h_buf1);
    cudaGetSymbolAddress((void**)&x4n, g_x4n);
    cudaGetSymbolAddress((void**)&x4l, g_x4l);
    cudaGetSymbolAddress((void**)&xn,  h_xn);
    cudaGetSymbolAddress((void**)&xl,  h_xl);
    cudaGetSymbolAddress((void**)&wt,  h_wt);

    const int M = BATCH;
    cudaFuncSetAttribute(gemm_mma<true>,  cudaFuncAttributeMaxDynamicSharedMemorySize, SMEM_BYTES);
    cudaFuncSetAttribute(gemm_mma<false>, cudaFuncAttributeMaxDynamicSharedMemorySize, SMEM_BYTES);

    const dim3 gemm_blk(128);   // gemm_mma CTA size
    const dim3 head_blk(256);   // head_kernel CTA size (grid math below assumes 256!)

    // launch 1: head precompute
    precompute_head<<<1, 512>>>(nW5, nb5, lW5, lb5, wreg);

    // launch 2: fused f32->fp16 prepass (inputs + weights)
    CvtArgs ca;
    ca.src[0] = node_x;  ca.dst[0] = xn;            ca.n4[0] = BATCH * 256 / 4;
    ca.src[1] = layer_x; ca.dst[1] = xl;            ca.n4[1] = BATCH * 16 / 4;
    ca.src[2] = nW1;     ca.dst[2] = wt + OFF_NW1;  ca.n4[2] = 256 * 256 / 4;
    ca.src[3] = nW2;     ca.dst[3] = wt + OFF_NW2;  ca.n4[3] = 512 * 256 / 4;
    ca.src[4] = nW3;     ca.dst[4] = wt + OFF_NW3;  ca.n4[4] = 1024 * 512 / 4;
    ca.src[5] = nW4;     ca.dst[5] = wt + OFF_NW4;  ca.n4[5] = 512 * 1024 / 4;
    ca.src[6] = lW1;     ca.dst[6] = wt + OFF_LW1;  ca.n4[6] = 256 * 16 / 4;
    ca.src[7] = lW2;     ca.dst[7] = wt + OFF_LW2;  ca.n4[7] = 512 * 256 / 4;
    ca.src[8] = lW3;     ca.dst[8] = wt + OFF_LW3;  ca.n4[8] = 1024 * 512 / 4;
    ca.src[9] = lW4;     ca.dst[9] = wt + OFF_LW4;  ca.n4[9] = 512 * 1024 / 4;
    cvt_all_kernel<<<2048, 256>>>(ca);

    // launches 3-6: node tower (relu layers 1-4; layer 5 collapsed into head)
    gemm_mma<false><<<dim3(256/128,  M/128), gemm_blk, SMEM_BYTES>>>(xn,  wt + OFF_NW1, nb1, b0h, M, 256, 256);
    gemm_mma<false><<<dim3(512/128,  M/128), gemm_blk, SMEM_BYTES>>>(b0h, wt + OFF_NW2, nb2, b1h, M, 512, 256);
    gemm_mma<false><<<dim3(1024/128, M/128), gemm_blk, SMEM_BYTES>>>(b1h, wt + OFF_NW3, nb3, b0h, M, 1024, 512);
    gemm_mma<true ><<<dim3(512/128,  M/128), gemm_blk, SMEM_BYTES>>>(b0h, wt + OFF_NW4, nb4, x4n, M, 512, 1024);

    // launches 7-10: layer tower
    gemm_mma<false><<<dim3(256/128,  M/128), gemm_blk, SMEM_BYTES>>>(xl,  wt + OFF_LW1, lb1, b0h, M, 256, 16);
    gemm_mma<false><<<dim3(512/128,  M/128), gemm_blk, SMEM_BYTES>>>(b0h, wt + OFF_LW2, lb2, b1h, M, 512, 256);
    gemm_mma<false><<<dim3(1024/128, M/128), gemm_blk, SMEM_BYTES>>>(b1h, wt + OFF_LW3, lb3, b0h, M, 1024, 512);
    gemm_mma<true ><<<dim3(512/128,  M/128), gemm_blk, SMEM_BYTES>>>(b0h, wt + OFF_LW4, lb4, x4l, M, 512, 1024);

    // launch 11: fused collapsed head — grid sized for 256-thread blocks (8 warps/block)
    head_kernel<<<(BATCH * 32) / 256, head_blk>>>(x4n, x4l, out);
}

// round 17
// speedup vs baseline: 1.8779x; 1.0491x over previous
#include <cuda_runtime.h>
#include <cuda_fp16.h>
#include <cstdint>

#define BATCH 32768

// ---------------- scratch (static device globals; no allocs allowed) ----------------
__device__ __align__(16) __half h_buf0[BATCH * 1024];   // node tower ping-pong
__device__ __align__(16) __half h_buf1[BATCH * 1024];
__device__ __align__(16) __half h_buf2[BATCH * 1024];   // layer tower ping-pong
__device__ __align__(16) __half h_buf3[BATCH * 1024];
__device__ __align__(16) float  g_x4n [BATCH * 512];    // node tower final (f32, head input)
__device__ __align__(16) float  g_x4l [BATCH * 512];    // layer tower final (f32, head input)
__device__ __align__(16) __half h_xn  [BATCH * 256];    // fp16 node_x
__device__ __align__(16) __half h_xl  [BATCH * 16];     // fp16 layer_x
__device__ __align__(16) __half h_wt  [2428928];        // fp16 weights (8 mats)
__device__ __align__(16) float  g_wn[512];
__device__ __align__(16) float  g_wl[512];
__device__ float g_sc[2];   // [0]=bn (mean of nb5), [1]=bl (wreg . lb5)

// weight offsets inside h_wt
#define OFF_NW1 0
#define OFF_NW2 65536
#define OFF_NW3 196608
#define OFF_NW4 720896
#define OFF_LW1 1245184
#define OFF_LW2 1249280
#define OFF_LW3 1380352
#define OFF_LW4 1904640

__device__ __forceinline__ uint32_t smem_u32(const void* p) {
    uint32_t a;
    asm("{ .reg .u64 t; cvta.to.shared.u64 t, %1; cvt.u32.u64 %0, t; }" : "=r"(a) : "l"(p));
    return a;
}

// cp.async 16B with register src-size (0 => zero-fill 16B)
__device__ __forceinline__ void cp16(uint32_t dst, const void* src, int src_size) {
    asm volatile("cp.async.cg.shared.global [%0], [%1], 16, %2;"
                 :: "r"(dst), "l"(src), "r"(src_size));
}
#define CP_COMMIT() asm volatile("cp.async.commit_group;" ::: "memory")
#define CP_WAIT0()  asm volatile("cp.async.wait_group 0;" ::: "memory")
#define CP_WAIT1()  asm volatile("cp.async.wait_group 1;" ::: "memory")

// ldmatrix m8n8.b16: lane l gets 2 halves at (row l/4, cols 2(l%4)..+1) of each 8x8 tile.
__device__ __forceinline__ void ldsm_x4(uint32_t& r0, uint32_t& r1, uint32_t& r2, uint32_t& r3,
                                        uint32_t addr) {
    asm volatile("ldmatrix.sync.aligned.m8n8.x4.shared.b16 {%0,%1,%2,%3}, [%4];"
                 : "=r"(r0), "=r"(r1), "=r"(r2), "=r"(r3) : "r"(addr));
}

// ---------------- fused f32->fp16 rounding prepass (single launch) ----------------
struct CvtArgs {
    const float* src[10];
    __half*      dst[10];
    int          n4[10];    // element count / 4
};

__global__ __launch_bounds__(256)
void cvt_all_kernel(CvtArgs a)
{
    const int tid    = blockIdx.x * 256 + threadIdx.x;
    const int stride = gridDim.x * 256;
    #pragma unroll
    for (int s = 0; s < 10; ++s) {
        const float4* sp = (const float4*)a.src[s];
        __half2*      dp = (__half2*)a.dst[s];
        const int n4 = a.n4[s];
        for (int i = tid; i < n4; i += stride) {
            float4 v = sp[i];
            dp[2*i]   = __floats2half2_rn(v.x, v.y);
            dp[2*i+1] = __floats2half2_rn(v.z, v.w);
        }
    }
}

// ---------------- head-collapse precompute ----------------
// w_n[k] = mean_o nW5[o,k]; w_l[k] = sum_o wreg[o]*lW5[o,k]
__global__ void precompute_head(const float* __restrict__ nW5, const float* __restrict__ nb5,
                                const float* __restrict__ lW5, const float* __restrict__ lb5,
                                const float* __restrict__ wreg)
{
    int k = threadIdx.x;                // 512 threads
    float s1 = 0.f, s2 = 0.f;
    #pragma unroll 4
    for (int o = 0; o < 256; ++o) {
        s1 += nW5[o * 512 + k];
        s2 += wreg[o] * lW5[o * 512 + k];
    }
    g_wn[k] = s1 * (1.f / 256.f);
    g_wl[k] = s2;
    if (k == 0) {
        float b = 0.f;
        for (int o = 0; o < 256; ++o) b += nb5[o];
        g_sc[0] = b * (1.f / 256.f);
    }
    if (k == 1) {
        float b = 0.f;
        for (int o = 0; o < 256; ++o) b += wreg[o] * lb5[o];
        g_sc[1] = b;
    }
}

// ================= fp16 mma.sync GEMM v8 (tower-fused via blockIdx.z) ============
// One launch runs BOTH towers' same-depth layers: blockIdx.z selects operand set.
// C[M,N] = relu(A @ W^T + bias); fp16 in, f32 accumulate.
// F32OUT: C is float (head inputs); else __half (next layer's A).
// CTA 128x128, BK=64, 128 threads (4 warps 2x2, warp tile 64x64), 2 CTAs/SM.
// 3-stage cp.async, 1 sync/tile; per k16-step: 8 ldsm.x4 + 32 MMA per warp.

struct PairArgs {
    const __half* A[2];
    const __half* W[2];
    const float*  bias[2];
    void*         C[2];
    int           K[2];
    int           N;        // shared across z
};

#define ROW_H      72                       // halves per row (64 + 8 pad); 144B stride
#define MAT_BYTES  (128 * ROW_H * 2)        // 18432 B
#define BUF_BYTES  (2 * MAT_BYTES)          // A + B per buffer: 36864 B
#define NSTAGE     3
#define SMEM_BYTES (NSTAGE * BUF_BYTES)     // 110592 B

__device__ __forceinline__ void mma_f16(float* c, const uint32_t* a, const uint32_t* b) {
    asm volatile(
        "mma.sync.aligned.m16n8k16.row.col.f32.f16.f16.f32 "
        "{%0,%1,%2,%3}, {%4,%5,%6,%7}, {%8,%9}, {%0,%1,%2,%3};"
        : "+f"(c[0]), "+f"(c[1]), "+f"(c[2]), "+f"(c[3])
        : "r"(a[0]), "r"(a[1]), "r"(a[2]), "r"(a[3]), "r"(b[0]), "r"(b[1]));
}

template <bool F32OUT>
__global__ __launch_bounds__(128, 2)
void gemm_pair(PairArgs p)
{
    extern __shared__ __half sm[];   // [stage][A|B][128][ROW_H]

    const int z    = blockIdx.z;
    const __half* __restrict__ A    = p.A[z];
    const __half* __restrict__ W    = p.W[z];
    const float*  __restrict__ bias = p.bias[z];
    void*  Cv = p.C[z];
    const int K = p.K[z];
    const int N = p.N;

    const int t    = threadIdx.x;
    const int lane = t & 31;
    const int wid  = t >> 5;            // 0..3
    const int bm   = blockIdx.y * 128;
    const int bn   = blockIdx.x * 128;
    const int wm   = (wid >> 1) * 64;   // warp M offset (0 or 64)
    const int wn   = (wid & 1) * 64;    // warp N offset (0 or 64)
    const int gid  = lane >> 2;         // 0..7
    const int tg   = lane & 3;          // 0..3

    // cp.async geometry: per matrix tile 128 rows x 64 halves = 1024 x 16B chunks;
    // 128 threads -> 8 chunks/thread/matrix.
    const int g_row = t >> 3;           // base row 0..15 (+16*j)
    const int g_c8  = (t & 7) << 3;     // k half-offset 0,8,...,56

    const uint32_t sbase = smem_u32(sm);
    const uint32_t d_off = (uint32_t)(g_row * ROW_H + g_c8) * 2;

    // ldmatrix per-lane byte offsets (relative to matrix base, 144B row stride)
    // A (.x4) tile mi (m16 x k16): row = wm+16mi+(lane&15), k-half = (lane>>4)*8
    // B (.x4) pair nj (n-tiles 2nj,2nj+1): row = wn+16nj+(lane&7)+((lane>>4)<<3),
    //   k-half = ((lane>>3)&1)*8
    uint32_t a_off[4], b_off[4];
    {
        const int ar = lane & 15;
        const int ac = (lane >> 4) << 3;                   // halves
        const int br = (lane & 7) + ((lane >> 4) << 3);
        const int bc = ((lane >> 3) & 1) << 3;             // halves
        #pragma unroll
        for (int mi = 0; mi < 4; ++mi)
            a_off[mi] = (uint32_t)(((wm + (mi << 4) + ar) * ROW_H + ac) * 2);
        #pragma unroll
        for (int nj = 0; nj < 4; ++nj)
            b_off[nj] = (uint32_t)(((wn + (nj << 4) + br) * ROW_H + bc) * 2);
    }

    float acc[4][8][4] = {};            // [mi][ni][c0..c3]
    const int nkt = (K + 63) >> 6;

    auto cp_tile = [&](int kt, int buf) {
        const int k0 = kt << 6;
        const bool ok = (k0 + g_c8 + 7) < K;
        const int sz = ok ? 16 : 0;
        const int koff = ok ? (k0 + g_c8) : 0;       // safe base when zero-filling
        const uint32_t dA = sbase + buf * BUF_BYTES + d_off;
        const uint32_t dB = dA + MAT_BYTES;
        const __half* Ap = A + (long)(bm + g_row) * K + koff;
        const __half* Wp = W + (long)(bn + g_row) * K + koff;
        #pragma unroll
        for (int j = 0; j < 8; ++j) {
            cp16(dA + j * 16 * (ROW_H * 2), Ap + (long)j * 16 * K, sz);
            cp16(dB + j * 16 * (ROW_H * 2), Wp + (long)j * 16 * K, sz);
        }
    };

    // ---- prologue: stage tiles 0 and 1 ----
    cp_tile(0, 0);
    CP_COMMIT();
    if (1 < nkt) { cp_tile(1, 1); CP_COMMIT(); }

    int buf = 0;
    for (int kt = 0; kt < nkt; ++kt) {
        if (kt + 1 < nkt) CP_WAIT1(); else CP_WAIT0();
        __syncthreads();                 // data visible + tile kt-1 readers retired

        if (kt + 2 < nkt) {              // prefetch into buffer of retired tile kt-1
            cp_tile(kt + 2, (buf + 2 >= NSTAGE) ? (buf + 2 - NSTAGE) : (buf + 2));
            CP_COMMIT();
        }

        const uint32_t as_u = sbase + buf * BUF_BYTES;
        const uint32_t bs_u = as_u + MAT_BYTES;

        #pragma unroll
        for (int ks = 0; ks < 4; ++ks) {
            const uint32_t kb = (uint32_t)(ks << 5);   // 16 halves * 2B per k16-step
            uint32_t af[4][4], bf[8][2];
            #pragma unroll
            for (int mi = 0; mi < 4; ++mi)
                ldsm_x4(af[mi][0], af[mi][1], af[mi][2], af[mi][3], as_u + a_off[mi] + kb);
            #pragma unroll
            for (int nj = 0; nj < 4; ++nj)
                ldsm_x4(bf[2*nj][0], bf[2*nj][1], bf[2*nj+1][0], bf[2*nj+1][1],
                        bs_u + b_off[nj] + kb);
            #pragma unroll
            for (int mi = 0; mi < 4; ++mi)
                #pragma unroll
                for (int ni = 0; ni < 8; ++ni)
                    mma_f16(acc[mi][ni], af[mi], bf[ni]);
        }

        buf = (buf + 1 == NSTAGE) ? 0 : (buf + 1);
    }

    // ---- epilogue: bias + relu; store f32 (head input) or fp16 (next layer) ----
    #pragma unroll
    for (int mi = 0; mi < 4; ++mi) {
        const long row0 = bm + wm + (mi << 4) + gid;
        const long row1 = row0 + 8;
        #pragma unroll
        for (int ni = 0; ni < 8; ++ni) {
            const int col = bn + wn + (ni << 3) + (tg << 1);
            const float b0 = __ldg(bias + col);
            const float b1 = __ldg(bias + col + 1);
            float v0 = fmaxf(acc[mi][ni][0] + b0, 0.f);
            float v1 = fmaxf(acc[mi][ni][1] + b1, 0.f);
            float v2 = fmaxf(acc[mi][ni][2] + b0, 0.f);
            float v3 = fmaxf(acc[mi][ni][3] + b1, 0.f);
            if (F32OUT) {
                float* C = (float*)Cv;
                *(float2*)(C + row0 * N + col) = make_float2(v0, v1);
                *(float2*)(C + row1 * N + col) = make_float2(v2, v3);
            } else {
                __half* C = (__half*)Cv;
                *(__half2*)(C + row0 * N + col) = __floats2half2_rn(v0, v1);
                *(__half2*)(C + row1 * N + col) = __floats2half2_rn(v2, v3);
            }
        }
    }
}

// ---------------- fused head: out[b] = (x4n[b].wn + bn) * (x4l[b].wl + bl) ----------------
__global__ __launch_bounds__(256)
void head_kernel(const float* __restrict__ xn, const float* __restrict__ xl,
                 float* __restrict__ out)
{
    int warp = (blockIdx.x * 256 + threadIdx.x) >> 5;
    int lane = threadIdx.x & 31;
    if (warp >= BATCH) return;

    const float4* pn = (const float4*)(xn + (long)warp * 512);
    const float4* pl = (const float4*)(xl + (long)warp * 512);
    const float4* wn = (const float4*)g_wn;
    const float4* wl = (const float4*)g_wl;

    float sn = 0.f, sl = 0.f;
    #pragma unroll
    for (int i = lane; i < 128; i += 32) {
        float4 a = pn[i], w = wn[i];
        sn += a.x * w.x + a.y * w.y + a.z * w.z + a.w * w.w;
        float4 b = pl[i], v = wl[i];
        sl += b.x * v.x + b.y * v.y + b.z * v.z + b.w * v.w;
    }
    #pragma unroll
    for (int off = 16; off > 0; off >>= 1) {
        sn += __shfl_xor_sync(0xffffffffu, sn, off);
        sl += __shfl_xor_sync(0xffffffffu, sl, off);
    }
    if (lane == 0)
        out[warp] = (sn + g_sc[0]) * (sl + g_sc[1]);
}

// ---------------- launch ----------------
extern "C" void kernel_launch(void* const* d_in, const int* in_sizes, int n_in,
                              void* d_out, int out_size)
{
    const float* node_x = (const float*)d_in[0];   // [B,256]
    const float* layer_x= (const float*)d_in[1];   // [B,16]
    const float* nW1 = (const float*)d_in[2];  const float* nb1 = (const float*)d_in[3];
    const float* nW2 = (const float*)d_in[4];  const float* nb2 = (const float*)d_in[5];
    const float* nW3 = (const float*)d_in[6];  const float* nb3 = (const float*)d_in[7];
    const float* nW4 = (const float*)d_in[8];  const float* nb4 = (const float*)d_in[9];
    const float* nW5 = (const float*)d_in[10]; const float* nb5 = (const float*)d_in[11];
    const float* lW1 = (const float*)d_in[12]; const float* lb1 = (const float*)d_in[13];
    const float* lW2 = (const float*)d_in[14]; const float* lb2 = (const float*)d_in[15];
    const float* lW3 = (const float*)d_in[16]; const float* lb3 = (const float*)d_in[17];
    const float* lW4 = (const float*)d_in[18]; const float* lb4 = (const float*)d_in[19];
    const float* lW5 = (const float*)d_in[20]; const float* lb5 = (const float*)d_in[21];
    const float* wreg= (const float*)d_in[22]; // [256]
    float* out = (float*)d_out;

    __half *b0h, *b1h, *b2h, *b3h, *xn, *xl, *wt;
    float *x4n, *x4l;
    cudaGetSymbolAddress((void**)&b0h, h_buf0);
    cudaGetSymbolAddress((void**)&b1h, h_buf1);
    cudaGetSymbolAddress((void**)&b2h, h_buf2);
    cudaGetSymbolAddress((void**)&b3h, h_buf3);
    cudaGetSymbolAddress((void**)&x4n, g_x4n);
    cudaGetSymbolAddress((void**)&x4l, g_x4l);
    cudaGetSymbolAddress((void**)&xn,  h_xn);
    cudaGetSymbolAddress((void**)&xl,  h_xl);
    cudaGetSymbolAddress((void**)&wt,  h_wt);

    const int M = BATCH;
    cudaFuncSetAttribute(gemm_pair<true>,  cudaFuncAttributeMaxDynamicSharedMemorySize, SMEM_BYTES);
    cudaFuncSetAttribute(gemm_pair<false>, cudaFuncAttributeMaxDynamicSharedMemorySize, SMEM_BYTES);

    const dim3 gemm_blk(128);   // gemm_pair CTA size
    const dim3 head_blk(256);   // head_kernel CTA size (grid math below assumes 256!)

    // launch 1: head precompute
    precompute_head<<<1, 512>>>(nW5, nb5, lW5, lb5, wreg);

    // launch 2: fused f32->fp16 prepass (inputs + weights)
    CvtArgs ca;
    ca.src[0] = node_x;  ca.dst[0] = xn;            ca.n4[0] = BATCH * 256 / 4;
    ca.src[1] = layer_x; ca.dst[1] = xl;            ca.n4[1] = BATCH * 16 / 4;
    ca.src[2] = nW1;     ca.dst[2] = wt + OFF_NW1;  ca.n4[2] = 256 * 256 / 4;
    ca.src[3] = nW2;     ca.dst[3] = wt + OFF_NW2;  ca.n4[3] = 512 * 256 / 4;
    ca.src[4] = nW3;     ca.dst[4] = wt + OFF_NW3;  ca.n4[4] = 1024 * 512 / 4;
    ca.src[5] = nW4;     ca.dst[5] = wt + OFF_NW4;  ca.n4[5] = 512 * 1024 / 4;
    ca.src[6] = lW1;     ca.dst[6] = wt + OFF_LW1;  ca.n4[6] = 256 * 16 / 4;
    ca.src[7] = lW2;     ca.dst[7] = wt + OFF_LW2;  ca.n4[7] = 512 * 256 / 4;
    ca.src[8] = lW3;     ca.dst[8] = wt + OFF_LW3;  ca.n4[8] = 1024 * 512 / 4;
    ca.src[9] = lW4;     ca.dst[9] = wt + OFF_LW4;  ca.n4[9] = 512 * 1024 / 4;
    cvt_all_kernel<<<2048, 256>>>(ca);

    // launches 3-6: fused tower pairs (z=0 node, z=1 layer)
    {   // depth 1: N=256; K = 256 (node) / 16 (layer)
        PairArgs p;
        p.A[0] = xn;  p.W[0] = wt + OFF_NW1; p.bias[0] = nb1; p.C[0] = b0h; p.K[0] = 256;
        p.A[1] = xl;  p.W[1] = wt + OFF_LW1; p.bias[1] = lb1; p.C[1] = b2h; p.K[1] = 16;
        p.N = 256;
        gemm_pair<false><<<dim3(256/128, M/128, 2), gemm_blk, SMEM_BYTES>>>(p);
    }
    {   // depth 2: N=512, K=256
        PairArgs p;
        p.A[0] = b0h; p.W[0] = wt + OFF_NW2; p.bias[0] = nb2; p.C[0] = b1h; p.K[0] = 256;
        p.A[1] = b2h; p.W[1] = wt + OFF_LW2; p.bias[1] = lb2; p.C[1] = b3h; p.K[1] = 256;
        p.N = 512;
        gemm_pair<false><<<dim3(512/128, M/128, 2), gemm_blk, SMEM_BYTES>>>(p);
    }
    {   // depth 3: N=1024, K=512
        PairArgs p;
        p.A[0] = b1h; p.W[0] = wt + OFF_NW3; p.bias[0] = nb3; p.C[0] = b0h; p.K[0] = 512;
        p.A[1] = b3h; p.W[1] = wt + OFF_LW3; p.bias[1] = lb3; p.C[1] = b2h; p.K[1] = 512;
        p.N = 1024;
        gemm_pair<false><<<dim3(1024/128, M/128, 2), gemm_blk, SMEM_BYTES>>>(p);
    }
    {   // depth 4: N=512, K=1024; f32 outputs feed the head
        PairArgs p;
        p.A[0] = b0h; p.W[0] = wt + OFF_NW4; p.bias[0] = nb4; p.C[0] = x4n; p.K[0] = 1024;
        p.A[1] = b2h; p.W[1] = wt + OFF_LW4; p.bias[1] = lb4; p.C[1] = x4l; p.K[1] = 1024;
        p.N = 512;
        gemm_pair<true><<<dim3(512/128, M/128, 2), gemm_blk, SMEM_BYTES>>>(p);
    }

    // launch 7: fused collapsed head — grid sized for 256-thread blocks (8 warps/block)
    head_kernel<<<(BATCH * 32) / 256, head_blk>>>(x4n, x4l, out);
}